// round 14
// baseline (speedup 1.0000x reference)
#include <cuda_runtime.h>
#include <cuda_bf16.h>

#define S_   2048
#define D_   1024
#define H_   16
#define B_   4
#define ROWS (B_*S_)
#define NX   (B_*S_*D_)     // 8388608 elems per q/k/v tensor
#define NW   (D_*D_)        // 1048576 elems per weight
#define LOG2E 1.4426950408889634f

// Scratch (allocation-free): module .bss, all bf16
__device__ __nv_bfloat16 g_Xb[(size_t)3*NX];   // q,k,v in bf16
__device__ __nv_bfloat16 g_Wb[(size_t)4*NW];   // Wq,Wk,Wv,Wo in bf16
__device__ __nv_bfloat16 g_Qh[(size_t)B_*H_*S_*64];
__device__ __nv_bfloat16 g_Kh[(size_t)B_*H_*S_*64];
__device__ __nv_bfloat16 g_Vh[(size_t)B_*H_*S_*64];
__device__ __nv_bfloat16 g_ctx[(size_t)ROWS*D_];

__device__ __forceinline__ float ex2f(float x) {
    float y; asm("ex2.approx.f32 %0, %1;" : "=f"(y) : "f"(x)); return y;
}
__device__ __forceinline__ unsigned pk2(float a, float b) {
    __nv_bfloat162 h = __float22bfloat162_rn(make_float2(a, b));
    return *reinterpret_cast<unsigned*>(&h);
}
__device__ __forceinline__ void mma16(float* c, const unsigned* a, const unsigned* b) {
    asm volatile(
        "mma.sync.aligned.m16n8k16.row.col.f32.bf16.bf16.f32 "
        "{%0,%1,%2,%3},{%4,%5,%6,%7},{%8,%9},{%0,%1,%2,%3};\n"
        : "+f"(c[0]), "+f"(c[1]), "+f"(c[2]), "+f"(c[3])
        : "r"(a[0]), "r"(a[1]), "r"(a[2]), "r"(a[3]), "r"(b[0]), "r"(b[1]));
}
__device__ __forceinline__ void ldsm4(unsigned* r, unsigned addr) {
    asm volatile("ldmatrix.sync.aligned.m8n8.x4.shared.b16 {%0,%1,%2,%3}, [%4];\n"
        : "=r"(r[0]), "=r"(r[1]), "=r"(r[2]), "=r"(r[3]) : "r"(addr));
}
__device__ __forceinline__ void cpa16(unsigned saddr, const void* g) {
    asm volatile("cp.async.cg.shared.global [%0], [%1], 16;\n"
        :: "r"(saddr), "l"(g));
}

// ---------------------------------------------------------------------------
// fp32 -> bf16 conversion pre-pass: q,k,v -> g_Xb; Wq,Wk,Wv,Wo -> g_Wb
// ---------------------------------------------------------------------------
__global__ __launch_bounds__(256) void conv_kernel(
    const float* __restrict__ q, const float* __restrict__ k, const float* __restrict__ v,
    const float* __restrict__ wq, const float* __restrict__ wk,
    const float* __restrict__ wv, const float* __restrict__ wo)
{
    size_t e = ((size_t)blockIdx.x * 256 + threadIdx.x) * 4;
    const float* src;
    __nv_bfloat16* dst;
    if (e < (size_t)3 * NX) {
        int s = (int)(e / NX);
        src = (s == 0) ? q : ((s == 1) ? k : v);
        dst = g_Xb + (size_t)s * NX;
        e -= (size_t)s * NX;
    } else {
        size_t r = e - (size_t)3 * NX;
        int s = (int)(r / NW);
        src = (s == 0) ? wq : ((s == 1) ? wk : ((s == 2) ? wv : wo));
        dst = g_Wb + (size_t)s * NW;
        e = r - (size_t)s * NW;
    }
    float4 x = *(const float4*)(src + e);
    *(__nv_bfloat162*)(dst + e)     = __float22bfloat162_rn(make_float2(x.x, x.y));
    *(__nv_bfloat162*)(dst + e + 2) = __float22bfloat162_rn(make_float2(x.z, x.w));
}

// ---------------------------------------------------------------------------
// Shared GEMM mainloop: C[128x128] = A[128xD] @ B[128xD]^T (NT), bf16 mma.
// BK=64 (16 iterations -> half the barriers of BK=32). 3-stage cp.async
// pipeline, wait_group 1. Smem pitch 36 words/row: 4r mod 32 spans 8
// distinct 4-word bank groups -> all ldmatrix phases conflict-free.
// Fragment double-buffer across the 4 ks-steps (regs: 64 acc + 48 frags).
// 8 warps, 64x32 warp tiles.
// Stage layout: [A 128*36 | B 128*36] words = 36864 B; 3 stages = 110592 B.
// ---------------------------------------------------------------------------
#define STG_B   36864
#define GEMM_SMEM (3 * STG_B)

__device__ __forceinline__ void gemm_mainloop(
    const __nv_bfloat16* __restrict__ Ablk,   // + m0*D_
    const __nv_bfloat16* __restrict__ Bblk,   // + n0*D_
    float acc[4][4][4])
{
    extern __shared__ unsigned smem_u[];
    const unsigned sbase = (unsigned)__cvta_generic_to_shared(smem_u);
    const int t = threadIdx.x;
    const int warp = t >> 5, l = t & 31;
    const int wm = (warp >> 2) * 64, wn = (warp & 3) * 32;

    // loaders: thread t -> row t>>1, four 16B chunks at (t&1)*4 .. +3
    const int lrow = t >> 1, lc0 = (t & 1) * 4;
    const __nv_bfloat16* gA = Ablk + (size_t)lrow * D_ + lc0 * 8;
    const __nv_bfloat16* gB = Bblk + (size_t)lrow * D_ + lc0 * 8;
    const unsigned sA = sbase + (lrow * 36 + lc0 * 4) * 4;
    const unsigned sB = sA + 128 * 36 * 4;

    // ldmatrix lane addressing (word offsets within a stage)
    const int arow = (l & 7) + 8 * ((l >> 3) & 1);   // A: m8-pair select
    const int acw  = 4 * (l >> 4);                   // A: k16-half select
    const int brow = (l & 7) + 8 * (l >> 4);         // B: n8-pair select
    const int bcw  = 4 * ((l >> 3) & 1);             // B: k16-half select

#pragma unroll
    for (int mt = 0; mt < 4; mt++)
#pragma unroll
        for (int nt = 0; nt < 4; nt++)
#pragma unroll
            for (int i = 0; i < 4; i++) acc[mt][nt][i] = 0.f;

    // prefetch stages 0, 1
#pragma unroll
    for (int s = 0; s < 2; s++) {
        const int ko = s * 64;
        const unsigned so = s * STG_B;
#pragma unroll
        for (int i = 0; i < 4; i++) {
            cpa16(sA + so + i * 16, gA + ko + i * 8);
            cpa16(sB + so + i * 16, gB + ko + i * 8);
        }
        asm volatile("cp.async.commit_group;\n" ::: "memory");
    }

#pragma unroll 1
    for (int kt = 0; kt < 16; kt++) {
        if (kt < 15) asm volatile("cp.async.wait_group 1;\n" ::: "memory");
        else         asm volatile("cp.async.wait_group 0;\n" ::: "memory");
        __syncthreads();
        if (kt + 2 < 16) {
            const int ko = (kt + 2) * 64;
            const unsigned so = ((kt + 2) % 3) * STG_B;
#pragma unroll
            for (int i = 0; i < 4; i++) {
                cpa16(sA + so + i * 16, gA + ko + i * 8);
                cpa16(sB + so + i * 16, gB + ko + i * 8);
            }
            asm volatile("cp.async.commit_group;\n" ::: "memory");
        }
        const unsigned stA = sbase + (kt % 3) * STG_B;
        const unsigned stB = stA + 128 * 36 * 4;

        // fragment double-buffer across 4 ks-steps
        unsigned af[2][4][4], bq[2][2][4];
#pragma unroll
        for (int mt = 0; mt < 4; mt++)
            ldsm4(af[0][mt], stA + ((wm + mt * 16 + arow) * 36 + acw) * 4);
#pragma unroll
        for (int p = 0; p < 2; p++)
            ldsm4(bq[0][p], stB + ((wn + p * 16 + brow) * 36 + bcw) * 4);
#pragma unroll
        for (int ks = 0; ks < 4; ks++) {
            const int cu = ks & 1, nx = cu ^ 1;
            if (ks < 3) {
                const int kw = (ks + 1) * 8;
#pragma unroll
                for (int mt = 0; mt < 4; mt++)
                    ldsm4(af[nx][mt],
                          stA + ((wm + mt * 16 + arow) * 36 + kw + acw) * 4);
#pragma unroll
                for (int p = 0; p < 2; p++)
                    ldsm4(bq[nx][p],
                          stB + ((wn + p * 16 + brow) * 36 + kw + bcw) * 4);
            }
#pragma unroll
            for (int mt = 0; mt < 4; mt++)
#pragma unroll
                for (int nt = 0; nt < 4; nt++) {
                    unsigned bfr[2] = { bq[cu][nt >> 1][(nt & 1) * 2],
                                        bq[cu][nt >> 1][(nt & 1) * 2 + 1] };
                    mma16(acc[mt][nt], af[cu][mt], bfr);
                }
        }
    }
}

// ---------------------------------------------------------------------------
// QKV projection: O = X @ W^T; epilogue remaps to [b,h,s,64] bf16,
// Q folds 0.125*log2(e).
// ---------------------------------------------------------------------------
__global__ __launch_bounds__(256, 2) void proj_kernel()
{
    const int z = blockIdx.z;
    const __nv_bfloat16* X = g_Xb + (size_t)z * NX;
    const __nv_bfloat16* W = g_Wb + (size_t)z * NW;
    __nv_bfloat16* O = (z == 0) ? g_Qh : ((z == 1) ? g_Kh : g_Vh);
    const float scale = (z == 0) ? 0.125f * LOG2E : 1.0f;

    const int m0 = blockIdx.y * 128, n0 = blockIdx.x * 128;
    float acc[4][4][4];
    gemm_mainloop(X + (size_t)m0 * D_, W + (size_t)n0 * D_, acc);

    const int t = threadIdx.x;
    const int warp = t >> 5, l = t & 31, g = l >> 2, t4 = l & 3;
    const int wm = (warp >> 2) * 64, wn = (warp & 3) * 32;
#pragma unroll
    for (int mt = 0; mt < 4; mt++) {
        const int row = m0 + wm + mt * 16 + g;
        const int bb = row >> 11, s = row & 2047;
#pragma unroll
        for (int nt = 0; nt < 4; nt++) {
            const int col = n0 + wn + nt * 8 + 2 * t4;
            const int h = col >> 6, cl = col & 63;
            *(unsigned*)&O[(((size_t)bb * H_ + h) * S_ + s) * 64 + cl] =
                pk2(acc[mt][nt][0] * scale, acc[mt][nt][1] * scale);
            *(unsigned*)&O[(((size_t)bb * H_ + h) * S_ + (s + 8)) * 64 + cl] =
                pk2(acc[mt][nt][2] * scale, acc[mt][nt][3] * scale);
        }
    }
}

// ---------------------------------------------------------------------------
// Output projection + residual: out = ctx @ Wo^T + resid (fp32 out)
// ---------------------------------------------------------------------------
__global__ __launch_bounds__(256, 2) void oproj_kernel(
    const float* __restrict__ resid, float* __restrict__ out)
{
    const int m0 = blockIdx.y * 128, n0 = blockIdx.x * 128;
    float acc[4][4][4];
    gemm_mainloop(g_ctx + (size_t)m0 * D_,
                  g_Wb + (size_t)3 * NW + (size_t)n0 * D_, acc);

    const int t = threadIdx.x;
    const int warp = t >> 5, l = t & 31, g = l >> 2, t4 = l & 3;
    const int wm = (warp >> 2) * 64, wn = (warp & 3) * 32;
#pragma unroll
    for (int mt = 0; mt < 4; mt++) {
        const int row = m0 + wm + mt * 16 + g;
#pragma unroll
        for (int nt = 0; nt < 4; nt++) {
            const int col = n0 + wn + nt * 8 + 2 * t4;
            float2 r0 = *(const float2*)&resid[(size_t)row * D_ + col];
            float2 r1 = *(const float2*)&resid[(size_t)(row + 8) * D_ + col];
            *(float2*)&out[(size_t)row * D_ + col] =
                make_float2(acc[mt][nt][0] + r0.x, acc[mt][nt][1] + r0.y);
            *(float2*)&out[(size_t)(row + 8) * D_ + col] =
                make_float2(acc[mt][nt][2] + r1.x, acc[mt][nt][3] + r1.y);
        }
    }
}

// ---------------------------------------------------------------------------
// Flash attention, bf16 m16n8k16 (unchanged).
// ---------------------------------------------------------------------------
__global__ __launch_bounds__(128) void attn_kernel(const int* __restrict__ sen_len)
{
    __shared__ unsigned Ks[64 * 36];    // [key][d-pairs]
    __shared__ unsigned VsT[64 * 36];   // [d][key-pairs]

    const int bh = blockIdx.y;
    const int b = bh >> 4, h = bh & 15;
    const int q0 = blockIdx.x * 64;
    const __nv_bfloat16* Qg = g_Qh + (size_t)bh * S_ * 64;
    const __nv_bfloat16* Kg = g_Kh + (size_t)bh * S_ * 64;
    const __nv_bfloat16* Vg = g_Vh + (size_t)bh * S_ * 64;
    const int sen = sen_len[b];
    const int kv_len = min(q0 + 64, sen);

    const int t = threadIdx.x;
    const int warp = t >> 5, l = t & 31, g = l >> 2, t4 = l & 3;
    const int wq = warp * 16;
    const int row0 = q0 + wq + g, row1 = row0 + 8;

    unsigned qa[4][4];
    {
        const __nv_bfloat16* Qr0 = Qg + (size_t)row0 * 64;
        const __nv_bfloat16* Qr1 = Qg + (size_t)row1 * 64;
#pragma unroll
        for (int kt = 0; kt < 4; kt++) {
            qa[kt][0] = *(const unsigned*)&Qr0[16 * kt + 2 * t4];
            qa[kt][1] = *(const unsigned*)&Qr1[16 * kt + 2 * t4];
            qa[kt][2] = *(const unsigned*)&Qr0[16 * kt + 8 + 2 * t4];
            qa[kt][3] = *(const unsigned*)&Qr1[16 * kt + 8 + 2 * t4];
        }
    }

    float oacc[8][4];
#pragma unroll
    for (int nt = 0; nt < 8; nt++)
#pragma unroll
        for (int i = 0; i < 4; i++) oacc[nt][i] = 0.f;
    float m0r = -1e30f, m1r = -1e30f, l0r = 0.f, l1r = 0.f;

    const int kp = t & 31, db0 = t >> 5;

    for (int k0 = 0; k0 < kv_len; k0 += 64) {
        __syncthreads();
#pragma unroll
        for (int it = 0; it < 4; it++) {
            const int f = t + it * 128;
            const int row = f >> 3, qd = f & 7;
            *(uint4*)&Ks[row * 36 + qd * 4] =
                *(const uint4*)&Kg[(size_t)(k0 + row) * 64 + qd * 8];
        }
#pragma unroll
        for (int it = 0; it < 2; it++) {
            const int db = db0 + it * 4;
            union { uint4 u; unsigned short s[8]; } r0, r1;
            r0.u = *(const uint4*)&Vg[(size_t)(k0 + 2 * kp) * 64 + db * 8];
            r1.u = *(const uint4*)&Vg[(size_t)(k0 + 2 * kp + 1) * 64 + db * 8];
#pragma unroll
            for (int j = 0; j < 8; j++)
                VsT[(db * 8 + j) * 36 + kp] =
                    (unsigned)r0.s[j] | ((unsigned)r1.s[j] << 16);
        }
        __syncthreads();

        float sacc[8][4];
#pragma unroll
        for (int nt = 0; nt < 8; nt++)
#pragma unroll
            for (int i = 0; i < 4; i++) sacc[nt][i] = 0.f;
#pragma unroll
        for (int kt = 0; kt < 4; kt++)
#pragma unroll
            for (int nt = 0; nt < 8; nt++) {
                unsigned bf[2];
                bf[0] = Ks[(nt * 8 + g) * 36 + kt * 8 + t4];
                bf[1] = Ks[(nt * 8 + g) * 36 + kt * 8 + t4 + 4];
                mma16(sacc[nt], qa[kt], bf);
            }

        if ((k0 + 63 > row0 - g) || (k0 + 64 > sen)) {
#pragma unroll
            for (int nt = 0; nt < 8; nt++) {
                const int c = k0 + nt * 8 + 2 * t4;
                if (c > row0     || c >= sen)     sacc[nt][0] = -1e9f;
                if (c + 1 > row0 || c + 1 >= sen) sacc[nt][1] = -1e9f;
                if (c > row1     || c >= sen)     sacc[nt][2] = -1e9f;
                if (c + 1 > row1 || c + 1 >= sen) sacc[nt][3] = -1e9f;
            }
        }

        float tm0 = -1e30f, tm1 = -1e30f;
#pragma unroll
        for (int nt = 0; nt < 8; nt++) {
            tm0 = fmaxf(tm0, fmaxf(sacc[nt][0], sacc[nt][1]));
            tm1 = fmaxf(tm1, fmaxf(sacc[nt][2], sacc[nt][3]));
        }
        tm0 = fmaxf(tm0, __shfl_xor_sync(0xffffffffu, tm0, 1));
        tm0 = fmaxf(tm0, __shfl_xor_sync(0xffffffffu, tm0, 2));
        tm1 = fmaxf(tm1, __shfl_xor_sync(0xffffffffu, tm1, 1));
        tm1 = fmaxf(tm1, __shfl_xor_sync(0xffffffffu, tm1, 2));
        const float mn0 = fmaxf(m0r, tm0), mn1 = fmaxf(m1r, tm1);
        const float a0 = ex2f(m0r - mn0), a1 = ex2f(m1r - mn1);
        m0r = mn0; m1r = mn1;
        float s0 = 0.f, s1 = 0.f;
#pragma unroll
        for (int nt = 0; nt < 8; nt++) {
            float p0 = ex2f(sacc[nt][0] - mn0);
            float p1 = ex2f(sacc[nt][1] - mn0);
            float p2 = ex2f(sacc[nt][2] - mn1);
            float p3 = ex2f(sacc[nt][3] - mn1);
            s0 += p0 + p1; s1 += p2 + p3;
            sacc[nt][0] = p0; sacc[nt][1] = p1; sacc[nt][2] = p2; sacc[nt][3] = p3;
            oacc[nt][0] *= a0; oacc[nt][1] *= a0;
            oacc[nt][2] *= a1; oacc[nt][3] *= a1;
        }
        s0 += __shfl_xor_sync(0xffffffffu, s0, 1);
        s0 += __shfl_xor_sync(0xffffffffu, s0, 2);
        s1 += __shfl_xor_sync(0xffffffffu, s1, 1);
        s1 += __shfl_xor_sync(0xffffffffu, s1, 2);
        l0r = l0r * a0 + s0;
        l1r = l1r * a1 + s1;

#pragma unroll
        for (int kt = 0; kt < 4; kt++) {
            unsigned pa[4];
            pa[0] = pk2(sacc[2 * kt][0],     sacc[2 * kt][1]);
            pa[1] = pk2(sacc[2 * kt][2],     sacc[2 * kt][3]);
            pa[2] = pk2(sacc[2 * kt + 1][0], sacc[2 * kt + 1][1]);
            pa[3] = pk2(sacc[2 * kt + 1][2], sacc[2 * kt + 1][3]);
#pragma unroll
            for (int nt = 0; nt < 8; nt++) {
                unsigned bf[2];
                bf[0] = VsT[(nt * 8 + g) * 36 + kt * 8 + t4];
                bf[1] = VsT[(nt * 8 + g) * 36 + kt * 8 + t4 + 4];
                mma16(oacc[nt], pa, bf);
            }
        }
    }

    const float inv0 = 1.f / l0r, inv1 = 1.f / l1r;
#pragma unroll
    for (int nt = 0; nt < 8; nt++) {
        const int cl = h * 64 + nt * 8 + 2 * t4;
        *(unsigned*)&g_ctx[((size_t)b * S_ + row0) * D_ + cl] =
            pk2(oacc[nt][0] * inv0, oacc[nt][1] * inv0);
        *(unsigned*)&g_ctx[((size_t)b * S_ + row1) * D_ + cl] =
            pk2(oacc[nt][2] * inv1, oacc[nt][3] * inv1);
    }
}

// ---------------------------------------------------------------------------
// LayerNorm (biased variance), in place. One block per 1024-elem row.
// ---------------------------------------------------------------------------
__global__ __launch_bounds__(256) void ln_kernel(
    float* __restrict__ out, const float* __restrict__ gamma,
    const float* __restrict__ beta)
{
    __shared__ float sbuf[8], ssbuf[8], red[2];
    const int row = blockIdx.x;
    float* p = out + (size_t)row * D_;
    const int t = threadIdx.x;

    float4 x = *(const float4*)&p[t * 4];
    float s  = x.x + x.y + x.z + x.w;
    float ss = x.x * x.x + x.y * x.y + x.z * x.z + x.w * x.w;
#pragma unroll
    for (int off = 16; off; off >>= 1) {
        s  += __shfl_xor_sync(0xffffffffu, s, off);
        ss += __shfl_xor_sync(0xffffffffu, ss, off);
    }
    if ((t & 31) == 0) { sbuf[t >> 5] = s; ssbuf[t >> 5] = ss; }
    __syncthreads();
    if (t == 0) {
        float S = 0.f, SS = 0.f;
        for (int i = 0; i < 8; i++) { S += sbuf[i]; SS += ssbuf[i]; }
        red[0] = S; red[1] = SS;
    }
    __syncthreads();
    float mean = red[0] * (1.f / 1024.f);
    float var  = red[1] * (1.f / 1024.f) - mean * mean;
    float inv  = rsqrtf(var + 1e-5f);

    float4 gg = *(const float4*)&gamma[t * 4];
    float4 bb = *(const float4*)&beta[t * 4];
    float4 y;
    y.x = (x.x - mean) * inv * gg.x + bb.x;
    y.y = (x.y - mean) * inv * gg.y + bb.y;
    y.z = (x.z - mean) * inv * gg.z + bb.z;
    y.w = (x.w - mean) * inv * gg.w + bb.w;
    *(float4*)&p[t * 4] = y;
}

// ---------------------------------------------------------------------------
extern "C" void kernel_launch(void* const* d_in, const int* in_sizes, int n_in,
                              void* d_out, int out_size)
{
    const float* q     = (const float*)d_in[0];
    const float* k     = (const float*)d_in[1];
    const float* v     = (const float*)d_in[2];
    const float* Wq    = (const float*)d_in[3];
    const float* Wk    = (const float*)d_in[4];
    const float* Wv    = (const float*)d_in[5];
    const float* Wo    = (const float*)d_in[6];
    const float* gamma = (const float*)d_in[7];
    const float* beta  = (const float*)d_in[8];
    const int*   sen   = (const int*)d_in[9];
    float* out = (float*)d_out;

    cudaFuncSetAttribute(proj_kernel,
                         cudaFuncAttributeMaxDynamicSharedMemorySize, GEMM_SMEM);
    cudaFuncSetAttribute(oproj_kernel,
                         cudaFuncAttributeMaxDynamicSharedMemorySize, GEMM_SMEM);

    conv_kernel<<<(3 * NX + 4 * NW) / (4 * 256), 256>>>(q, k, v, Wq, Wk, Wv, Wo);
    proj_kernel<<<dim3(D_ / 128, ROWS / 128, 3), 256, GEMM_SMEM>>>();
    attn_kernel<<<dim3(S_ / 64, B_ * H_), 128>>>(sen);
    oproj_kernel<<<dim3(D_ / 128, ROWS / 128), 256, GEMM_SMEM>>>(q, out);
    ln_kernel<<<ROWS, 256>>>(out, gamma, beta);
}

// round 15
// speedup vs baseline: 1.0807x; 1.0807x over previous
#include <cuda_runtime.h>
#include <cuda_bf16.h>

#define S_   2048
#define D_   1024
#define H_   16
#define B_   4
#define ROWS (B_*S_)
#define NX   (B_*S_*D_)     // 8388608 elems per q/k/v tensor
#define NW   (D_*D_)        // 1048576 elems per weight
#define LOG2E 1.4426950408889634f

// Scratch (allocation-free): module .bss, all bf16
__device__ __nv_bfloat16 g_Xb[(size_t)3*NX];   // q,k,v in bf16
__device__ __nv_bfloat16 g_Wb[(size_t)4*NW];   // Wq,Wk,Wv,Wo in bf16
__device__ __nv_bfloat16 g_Qh[(size_t)B_*H_*S_*64];
__device__ __nv_bfloat16 g_Kh[(size_t)B_*H_*S_*64];
__device__ __nv_bfloat16 g_Vh[(size_t)B_*H_*S_*64];
__device__ __nv_bfloat16 g_ctx[(size_t)ROWS*D_];

__device__ __forceinline__ float ex2f(float x) {
    float y; asm("ex2.approx.f32 %0, %1;" : "=f"(y) : "f"(x)); return y;
}
__device__ __forceinline__ unsigned pk2(float a, float b) {
    __nv_bfloat162 h = __float22bfloat162_rn(make_float2(a, b));
    return *reinterpret_cast<unsigned*>(&h);
}
__device__ __forceinline__ void mma16(float* c, const unsigned* a, const unsigned* b) {
    asm volatile(
        "mma.sync.aligned.m16n8k16.row.col.f32.bf16.bf16.f32 "
        "{%0,%1,%2,%3},{%4,%5,%6,%7},{%8,%9},{%0,%1,%2,%3};\n"
        : "+f"(c[0]), "+f"(c[1]), "+f"(c[2]), "+f"(c[3])
        : "r"(a[0]), "r"(a[1]), "r"(a[2]), "r"(a[3]), "r"(b[0]), "r"(b[1]));
}
__device__ __forceinline__ void ldsm4(unsigned* r, unsigned addr) {
    asm volatile("ldmatrix.sync.aligned.m8n8.x4.shared.b16 {%0,%1,%2,%3}, [%4];\n"
        : "=r"(r[0]), "=r"(r[1]), "=r"(r[2]), "=r"(r[3]) : "r"(addr));
}
__device__ __forceinline__ void cpa16(unsigned saddr, const void* g) {
    asm volatile("cp.async.cg.shared.global [%0], [%1], 16;\n"
        :: "r"(saddr), "l"(g));
}

// ---------------------------------------------------------------------------
// fp32 -> bf16 conversion pre-pass: q,k,v -> g_Xb; Wq,Wk,Wv,Wo -> g_Wb
// ---------------------------------------------------------------------------
__global__ __launch_bounds__(256) void conv_kernel(
    const float* __restrict__ q, const float* __restrict__ k, const float* __restrict__ v,
    const float* __restrict__ wq, const float* __restrict__ wk,
    const float* __restrict__ wv, const float* __restrict__ wo)
{
    size_t e = ((size_t)blockIdx.x * 256 + threadIdx.x) * 4;
    const float* src;
    __nv_bfloat16* dst;
    if (e < (size_t)3 * NX) {
        int s = (int)(e / NX);
        src = (s == 0) ? q : ((s == 1) ? k : v);
        dst = g_Xb + (size_t)s * NX;
        e -= (size_t)s * NX;
    } else {
        size_t r = e - (size_t)3 * NX;
        int s = (int)(r / NW);
        src = (s == 0) ? wq : ((s == 1) ? wk : ((s == 2) ? wv : wo));
        dst = g_Wb + (size_t)s * NW;
        e = r - (size_t)s * NW;
    }
    float4 x = *(const float4*)(src + e);
    *(__nv_bfloat162*)(dst + e)     = __float22bfloat162_rn(make_float2(x.x, x.y));
    *(__nv_bfloat162*)(dst + e + 2) = __float22bfloat162_rn(make_float2(x.z, x.w));
}

// ---------------------------------------------------------------------------
// Shared GEMM mainloop: C[128x64] = A[128xD] @ B[64xD]^T (NT), bf16 mma.
// BK=32, 4-stage cp.async (wait_group 2, proven R13 shape). 8 warps,
// 32x32 warp tiles (warp grid 4x2) -> ~80 regs -> 3 CTAs/SM, 6 warps/SMSP.
// Smem pitch 20 words (ldmatrix phases conflict-free: 20r mod 32 spans
// 8 disjoint 4-word groups). Batched LDSM per kt (8 ldsm.x4 then 16 mma).
// Stage: A 128*20 + B 64*20 words = 15360 B; 4 stages = 61440 B.
// ---------------------------------------------------------------------------
#define STG_B 15360
#define GEMM_SMEM (4 * STG_B)

__device__ __forceinline__ void gemm_mainloop(
    const __nv_bfloat16* __restrict__ Ablk,   // + m0*D_
    const __nv_bfloat16* __restrict__ Bblk,   // + n0*D_
    float acc[2][4][4])
{
    extern __shared__ unsigned smem_u[];
    const unsigned sbase = (unsigned)__cvta_generic_to_shared(smem_u);
    const int t = threadIdx.x;
    const int warp = t >> 5, l = t & 31;
    const int wm = (warp >> 1) * 32, wn = (warp & 1) * 32;

    // loaders: A row t>>1 (2 chunks), B row t>>2 (1 chunk)
    const int larow = t >> 1, lac0 = (t & 1) * 2;
    const int lbrow = t >> 2, lbc = t & 3;
    const __nv_bfloat16* gA = Ablk + (size_t)larow * D_ + lac0 * 8;
    const __nv_bfloat16* gB = Bblk + (size_t)lbrow * D_ + lbc * 8;
    const unsigned sA = sbase + (larow * 20 + lac0 * 4) * 4;
    const unsigned sB = sbase + 128 * 80 + (lbrow * 20 + lbc * 4) * 4;

    // ldmatrix lane addressing (word offsets within a stage)
    const int arow = (l & 7) + 8 * ((l >> 3) & 1);   // A: m8-pair select
    const int acw  = 4 * (l >> 4);                   // A: k16-half select
    const int brow = (l & 7) + 8 * (l >> 4);         // B: n8-pair select
    const int bcw  = 4 * ((l >> 3) & 1);             // B: k16-half select

#pragma unroll
    for (int mt = 0; mt < 2; mt++)
#pragma unroll
        for (int nt = 0; nt < 4; nt++)
#pragma unroll
            for (int i = 0; i < 4; i++) acc[mt][nt][i] = 0.f;

    // prefetch stages 0..2
#pragma unroll
    for (int s = 0; s < 3; s++) {
        const int ko = s * 32;
        const unsigned so = s * STG_B;
        cpa16(sA + so, gA + ko);
        cpa16(sA + so + 16, gA + ko + 8);
        cpa16(sB + so, gB + ko);
        asm volatile("cp.async.commit_group;\n" ::: "memory");
    }

#pragma unroll 1
    for (int kt = 0; kt < 32; kt++) {
        if (kt < 30)       asm volatile("cp.async.wait_group 2;\n" ::: "memory");
        else if (kt == 30) asm volatile("cp.async.wait_group 1;\n" ::: "memory");
        else               asm volatile("cp.async.wait_group 0;\n" ::: "memory");
        __syncthreads();
        if (kt + 3 < 32) {
            const int ko = (kt + 3) * 32;
            const unsigned so = ((kt + 3) & 3) * STG_B;
            cpa16(sA + so, gA + ko);
            cpa16(sA + so + 16, gA + ko + 8);
            cpa16(sB + so, gB + ko);
            asm volatile("cp.async.commit_group;\n" ::: "memory");
        }
        const unsigned stA = sbase + (kt & 3) * STG_B;
        const unsigned stB = stA + 128 * 80;

        // batch ALL fragment loads (8 ldsm.x4), then the 16-mma stream
        unsigned af[2][2][4], bq[2][2][4];
#pragma unroll
        for (int ks = 0; ks < 2; ks++) {
#pragma unroll
            for (int mt = 0; mt < 2; mt++)
                ldsm4(af[ks][mt],
                      stA + ((wm + mt * 16 + arow) * 20 + ks * 8 + acw) * 4);
#pragma unroll
            for (int p = 0; p < 2; p++)
                ldsm4(bq[ks][p],
                      stB + ((wn + p * 16 + brow) * 20 + ks * 8 + bcw) * 4);
        }
#pragma unroll
        for (int ks = 0; ks < 2; ks++)
#pragma unroll
            for (int mt = 0; mt < 2; mt++)
#pragma unroll
                for (int nt = 0; nt < 4; nt++) {
                    unsigned bfr[2] = { bq[ks][nt >> 1][(nt & 1) * 2],
                                        bq[ks][nt >> 1][(nt & 1) * 2 + 1] };
                    mma16(acc[mt][nt], af[ks][mt], bfr);
                }
    }
}

// ---------------------------------------------------------------------------
// QKV projection: O = X @ W^T; CTA tile 128x64 (one head per tile).
// Epilogue remaps to [b,h,s,64] bf16; Q folds 0.125*log2(e).
// ---------------------------------------------------------------------------
__global__ __launch_bounds__(256, 3) void proj_kernel()
{
    const int z = blockIdx.z;
    const __nv_bfloat16* X = g_Xb + (size_t)z * NX;
    const __nv_bfloat16* W = g_Wb + (size_t)z * NW;
    __nv_bfloat16* O = (z == 0) ? g_Qh : ((z == 1) ? g_Kh : g_Vh);
    const float scale = (z == 0) ? 0.125f * LOG2E : 1.0f;

    const int m0 = blockIdx.y * 128, n0 = blockIdx.x * 64;
    float acc[2][4][4];
    gemm_mainloop(X + (size_t)m0 * D_, W + (size_t)n0 * D_, acc);

    const int t = threadIdx.x;
    const int warp = t >> 5, l = t & 31, g = l >> 2, t4 = l & 3;
    const int wm = (warp >> 1) * 32, wn = (warp & 1) * 32;
    const int h = blockIdx.x;   // 64-col tile == one head
#pragma unroll
    for (int mt = 0; mt < 2; mt++) {
        const int row = m0 + wm + mt * 16 + g;
        const int bb = row >> 11, s = row & 2047;
#pragma unroll
        for (int nt = 0; nt < 4; nt++) {
            const int cl = wn + nt * 8 + 2 * t4;
            *(unsigned*)&O[(((size_t)bb * H_ + h) * S_ + s) * 64 + cl] =
                pk2(acc[mt][nt][0] * scale, acc[mt][nt][1] * scale);
            *(unsigned*)&O[(((size_t)bb * H_ + h) * S_ + (s + 8)) * 64 + cl] =
                pk2(acc[mt][nt][2] * scale, acc[mt][nt][3] * scale);
        }
    }
}

// ---------------------------------------------------------------------------
// Output projection + residual: out = ctx @ Wo^T + resid (fp32 out)
// ---------------------------------------------------------------------------
__global__ __launch_bounds__(256, 3) void oproj_kernel(
    const float* __restrict__ resid, float* __restrict__ out)
{
    const int m0 = blockIdx.y * 128, n0 = blockIdx.x * 64;
    float acc[2][4][4];
    gemm_mainloop(g_ctx + (size_t)m0 * D_,
                  g_Wb + (size_t)3 * NW + (size_t)n0 * D_, acc);

    const int t = threadIdx.x;
    const int warp = t >> 5, l = t & 31, g = l >> 2, t4 = l & 3;
    const int wm = (warp >> 1) * 32, wn = (warp & 1) * 32;
#pragma unroll
    for (int mt = 0; mt < 2; mt++) {
        const int row = m0 + wm + mt * 16 + g;
#pragma unroll
        for (int nt = 0; nt < 4; nt++) {
            const int col = n0 + wn + nt * 8 + 2 * t4;
            float2 r0 = *(const float2*)&resid[(size_t)row * D_ + col];
            float2 r1 = *(const float2*)&resid[(size_t)(row + 8) * D_ + col];
            *(float2*)&out[(size_t)row * D_ + col] =
                make_float2(acc[mt][nt][0] + r0.x, acc[mt][nt][1] + r0.y);
            *(float2*)&out[(size_t)(row + 8) * D_ + col] =
                make_float2(acc[mt][nt][2] + r1.x, acc[mt][nt][3] + r1.y);
        }
    }
}

// ---------------------------------------------------------------------------
// Flash attention, bf16 m16n8k16. 128-query tile, 8 warps (per-warp math
// identical to the proven 64-tile version; K/V staging shared by 2x the
// queries -> half the staging traffic and barriers). Fully-masked extra
// blocks for lower warps are exact no-ops (p=0, alpha=1).
// ---------------------------------------------------------------------------
__global__ __launch_bounds__(256) void attn_kernel(const int* __restrict__ sen_len)
{
    __shared__ unsigned Ks[64 * 36];    // [key][d-pairs]
    __shared__ unsigned VsT[64 * 36];   // [d][key-pairs]

    const int bh = blockIdx.y;
    const int b = bh >> 4, h = bh & 15;
    const int q0 = blockIdx.x * 128;
    const __nv_bfloat16* Qg = g_Qh + (size_t)bh * S_ * 64;
    const __nv_bfloat16* Kg = g_Kh + (size_t)bh * S_ * 64;
    const __nv_bfloat16* Vg = g_Vh + (size_t)bh * S_ * 64;
    const int sen = sen_len[b];
    const int kv_len = min(q0 + 128, sen);

    const int t = threadIdx.x;
    const int warp = t >> 5, l = t & 31, g = l >> 2, t4 = l & 3;
    const int wq = warp * 16;
    const int row0 = q0 + wq + g, row1 = row0 + 8;

    unsigned qa[4][4];
    {
        const __nv_bfloat16* Qr0 = Qg + (size_t)row0 * 64;
        const __nv_bfloat16* Qr1 = Qg + (size_t)row1 * 64;
#pragma unroll
        for (int kt = 0; kt < 4; kt++) {
            qa[kt][0] = *(const unsigned*)&Qr0[16 * kt + 2 * t4];
            qa[kt][1] = *(const unsigned*)&Qr1[16 * kt + 2 * t4];
            qa[kt][2] = *(const unsigned*)&Qr0[16 * kt + 8 + 2 * t4];
            qa[kt][3] = *(const unsigned*)&Qr1[16 * kt + 8 + 2 * t4];
        }
    }

    float oacc[8][4];
#pragma unroll
    for (int nt = 0; nt < 8; nt++)
#pragma unroll
        for (int i = 0; i < 4; i++) oacc[nt][i] = 0.f;
    float m0r = -1e30f, m1r = -1e30f, l0r = 0.f, l1r = 0.f;

    const int kp = t & 31, db = t >> 5;   // V-transpose: key-pair, d-block

    for (int k0 = 0; k0 < kv_len; k0 += 64) {
        __syncthreads();
        // K: straight copy, 256 threads x 2 chunks
#pragma unroll
        for (int it = 0; it < 2; it++) {
            const int f = t + it * 256;
            const int row = f >> 3, qd = f & 7;
            *(uint4*)&Ks[row * 36 + qd * 4] =
                *(const uint4*)&Kg[(size_t)(k0 + row) * 64 + qd * 8];
        }
        // V: transpose during staging (each warp owns one 8-wide d-block)
        {
            union { uint4 u; unsigned short s[8]; } r0, r1;
            r0.u = *(const uint4*)&Vg[(size_t)(k0 + 2 * kp) * 64 + db * 8];
            r1.u = *(const uint4*)&Vg[(size_t)(k0 + 2 * kp + 1) * 64 + db * 8];
#pragma unroll
            for (int j = 0; j < 8; j++)
                VsT[(db * 8 + j) * 36 + kp] =
                    (unsigned)r0.s[j] | ((unsigned)r1.s[j] << 16);
        }
        __syncthreads();

        float sacc[8][4];
#pragma unroll
        for (int nt = 0; nt < 8; nt++)
#pragma unroll
            for (int i = 0; i < 4; i++) sacc[nt][i] = 0.f;
#pragma unroll
        for (int kt = 0; kt < 4; kt++)
#pragma unroll
            for (int nt = 0; nt < 8; nt++) {
                unsigned bf[2];
                bf[0] = Ks[(nt * 8 + g) * 36 + kt * 8 + t4];
                bf[1] = Ks[(nt * 8 + g) * 36 + kt * 8 + t4 + 4];
                mma16(sacc[nt], qa[kt], bf);
            }

        if ((k0 + 63 > row0 - g) || (k0 + 64 > sen)) {
#pragma unroll
            for (int nt = 0; nt < 8; nt++) {
                const int c = k0 + nt * 8 + 2 * t4;
                if (c > row0     || c >= sen)     sacc[nt][0] = -1e9f;
                if (c + 1 > row0 || c + 1 >= sen) sacc[nt][1] = -1e9f;
                if (c > row1     || c >= sen)     sacc[nt][2] = -1e9f;
                if (c + 1 > row1 || c + 1 >= sen) sacc[nt][3] = -1e9f;
            }
        }

        float tm0 = -1e30f, tm1 = -1e30f;
#pragma unroll
        for (int nt = 0; nt < 8; nt++) {
            tm0 = fmaxf(tm0, fmaxf(sacc[nt][0], sacc[nt][1]));
            tm1 = fmaxf(tm1, fmaxf(sacc[nt][2], sacc[nt][3]));
        }
        tm0 = fmaxf(tm0, __shfl_xor_sync(0xffffffffu, tm0, 1));
        tm0 = fmaxf(tm0, __shfl_xor_sync(0xffffffffu, tm0, 2));
        tm1 = fmaxf(tm1, __shfl_xor_sync(0xffffffffu, tm1, 1));
        tm1 = fmaxf(tm1, __shfl_xor_sync(0xffffffffu, tm1, 2));
        const float mn0 = fmaxf(m0r, tm0), mn1 = fmaxf(m1r, tm1);
        const float a0 = ex2f(m0r - mn0), a1 = ex2f(m1r - mn1);
        m0r = mn0; m1r = mn1;
        float s0 = 0.f, s1 = 0.f;
#pragma unroll
        for (int nt = 0; nt < 8; nt++) {
            float p0 = ex2f(sacc[nt][0] - mn0);
            float p1 = ex2f(sacc[nt][1] - mn0);
            float p2 = ex2f(sacc[nt][2] - mn1);
            float p3 = ex2f(sacc[nt][3] - mn1);
            s0 += p0 + p1; s1 += p2 + p3;
            sacc[nt][0] = p0; sacc[nt][1] = p1; sacc[nt][2] = p2; sacc[nt][3] = p3;
            oacc[nt][0] *= a0; oacc[nt][1] *= a0;
            oacc[nt][2] *= a1; oacc[nt][3] *= a1;
        }
        s0 += __shfl_xor_sync(0xffffffffu, s0, 1);
        s0 += __shfl_xor_sync(0xffffffffu, s0, 2);
        s1 += __shfl_xor_sync(0xffffffffu, s1, 1);
        s1 += __shfl_xor_sync(0xffffffffu, s1, 2);
        l0r = l0r * a0 + s0;
        l1r = l1r * a1 + s1;

#pragma unroll
        for (int kt = 0; kt < 4; kt++) {
            unsigned pa[4];
            pa[0] = pk2(sacc[2 * kt][0],     sacc[2 * kt][1]);
            pa[1] = pk2(sacc[2 * kt][2],     sacc[2 * kt][3]);
            pa[2] = pk2(sacc[2 * kt + 1][0], sacc[2 * kt + 1][1]);
            pa[3] = pk2(sacc[2 * kt + 1][2], sacc[2 * kt + 1][3]);
#pragma unroll
            for (int nt = 0; nt < 8; nt++) {
                unsigned bf[2];
                bf[0] = VsT[(nt * 8 + g) * 36 + kt * 8 + t4];
                bf[1] = VsT[(nt * 8 + g) * 36 + kt * 8 + t4 + 4];
                mma16(oacc[nt], pa, bf);
            }
        }
    }

    const float inv0 = 1.f / l0r, inv1 = 1.f / l1r;
#pragma unroll
    for (int nt = 0; nt < 8; nt++) {
        const int cl = h * 64 + nt * 8 + 2 * t4;
        *(unsigned*)&g_ctx[((size_t)b * S_ + row0) * D_ + cl] =
            pk2(oacc[nt][0] * inv0, oacc[nt][1] * inv0);
        *(unsigned*)&g_ctx[((size_t)b * S_ + row1) * D_ + cl] =
            pk2(oacc[nt][2] * inv1, oacc[nt][3] * inv1);
    }
}

// ---------------------------------------------------------------------------
// LayerNorm (biased variance), in place. One block per 1024-elem row.
// ---------------------------------------------------------------------------
__global__ __launch_bounds__(256) void ln_kernel(
    float* __restrict__ out, const float* __restrict__ gamma,
    const float* __restrict__ beta)
{
    __shared__ float sbuf[8], ssbuf[8], red[2];
    const int row = blockIdx.x;
    float* p = out + (size_t)row * D_;
    const int t = threadIdx.x;

    float4 x = *(const float4*)&p[t * 4];
    float s  = x.x + x.y + x.z + x.w;
    float ss = x.x * x.x + x.y * x.y + x.z * x.z + x.w * x.w;
#pragma unroll
    for (int off = 16; off; off >>= 1) {
        s  += __shfl_xor_sync(0xffffffffu, s, off);
        ss += __shfl_xor_sync(0xffffffffu, ss, off);
    }
    if ((t & 31) == 0) { sbuf[t >> 5] = s; ssbuf[t >> 5] = ss; }
    __syncthreads();
    if (t == 0) {
        float S = 0.f, SS = 0.f;
        for (int i = 0; i < 8; i++) { S += sbuf[i]; SS += ssbuf[i]; }
        red[0] = S; red[1] = SS;
    }
    __syncthreads();
    float mean = red[0] * (1.f / 1024.f);
    float var  = red[1] * (1.f / 1024.f) - mean * mean;
    float inv  = rsqrtf(var + 1e-5f);

    float4 gg = *(const float4*)&gamma[t * 4];
    float4 bb = *(const float4*)&beta[t * 4];
    float4 y;
    y.x = (x.x - mean) * inv * gg.x + bb.x;
    y.y = (x.y - mean) * inv * gg.y + bb.y;
    y.z = (x.z - mean) * inv * gg.z + bb.z;
    y.w = (x.w - mean) * inv * gg.w + bb.w;
    *(float4*)&p[t * 4] = y;
}

// ---------------------------------------------------------------------------
extern "C" void kernel_launch(void* const* d_in, const int* in_sizes, int n_in,
                              void* d_out, int out_size)
{
    const float* q     = (const float*)d_in[0];
    const float* k     = (const float*)d_in[1];
    const float* v     = (const float*)d_in[2];
    const float* Wq    = (const float*)d_in[3];
    const float* Wk    = (const float*)d_in[4];
    const float* Wv    = (const float*)d_in[5];
    const float* Wo    = (const float*)d_in[6];
    const float* gamma = (const float*)d_in[7];
    const float* beta  = (const float*)d_in[8];
    const int*   sen   = (const int*)d_in[9];
    float* out = (float*)d_out;

    cudaFuncSetAttribute(proj_kernel,
                         cudaFuncAttributeMaxDynamicSharedMemorySize, GEMM_SMEM);
    cudaFuncSetAttribute(oproj_kernel,
                         cudaFuncAttributeMaxDynamicSharedMemorySize, GEMM_SMEM);

    conv_kernel<<<(3 * NX + 4 * NW) / (4 * 256), 256>>>(q, k, v, Wq, Wk, Wv, Wo);
    proj_kernel<<<dim3(D_ / 64, ROWS / 128, 3), 256, GEMM_SMEM>>>();
    attn_kernel<<<dim3(S_ / 128, B_ * H_), 256>>>(sen);
    oproj_kernel<<<dim3(D_ / 64, ROWS / 128), 256, GEMM_SMEM>>>(q, out);
    ln_kernel<<<ROWS, 256>>>(out, gamma, beta);
}

// round 17
// speedup vs baseline: 1.2086x; 1.1183x over previous
#include <cuda_runtime.h>
#include <cuda_bf16.h>

#define S_   2048
#define D_   1024
#define H_   16
#define B_   4
#define ROWS (B_*S_)
#define NX   (B_*S_*D_)     // 8388608 elems per q/k/v tensor
#define NW   (D_*D_)        // 1048576 elems per weight
#define LOG2E 1.4426950408889634f

// Scratch (allocation-free): module .bss, all bf16
__device__ __nv_bfloat16 g_Xb[(size_t)3*NX];   // q,k,v in bf16
__device__ __nv_bfloat16 g_Wb[(size_t)4*NW];   // Wq,Wk,Wv,Wo in bf16
__device__ __nv_bfloat16 g_Qh[(size_t)B_*H_*S_*64];
__device__ __nv_bfloat16 g_Kh[(size_t)B_*H_*S_*64];
__device__ __nv_bfloat16 g_Vh[(size_t)B_*H_*S_*64];
__device__ __nv_bfloat16 g_ctx[(size_t)ROWS*D_];

__device__ __forceinline__ float ex2f(float x) {
    float y; asm("ex2.approx.f32 %0, %1;" : "=f"(y) : "f"(x)); return y;
}
__device__ __forceinline__ unsigned pk2(float a, float b) {
    __nv_bfloat162 h = __float22bfloat162_rn(make_float2(a, b));
    return *reinterpret_cast<unsigned*>(&h);
}
__device__ __forceinline__ void mma16(float* c, const unsigned* a, const unsigned* b) {
    asm volatile(
        "mma.sync.aligned.m16n8k16.row.col.f32.bf16.bf16.f32 "
        "{%0,%1,%2,%3},{%4,%5,%6,%7},{%8,%9},{%0,%1,%2,%3};\n"
        : "+f"(c[0]), "+f"(c[1]), "+f"(c[2]), "+f"(c[3])
        : "r"(a[0]), "r"(a[1]), "r"(a[2]), "r"(a[3]), "r"(b[0]), "r"(b[1]));
}
__device__ __forceinline__ void ldsm4(unsigned* r, unsigned addr) {
    asm volatile("ldmatrix.sync.aligned.m8n8.x4.shared.b16 {%0,%1,%2,%3}, [%4];\n"
        : "=r"(r[0]), "=r"(r[1]), "=r"(r[2]), "=r"(r[3]) : "r"(addr));
}
__device__ __forceinline__ void cpa16(unsigned saddr, const void* g) {
    asm volatile("cp.async.cg.shared.global [%0], [%1], 16;\n"
        :: "r"(saddr), "l"(g));
}

// ---------------------------------------------------------------------------
// fp32 -> bf16 conversion pre-pass: q,k,v -> g_Xb; Wq,Wk,Wv,Wo -> g_Wb
// ---------------------------------------------------------------------------
__global__ __launch_bounds__(256) void conv_kernel(
    const float* __restrict__ q, const float* __restrict__ k, const float* __restrict__ v,
    const float* __restrict__ wq, const float* __restrict__ wk,
    const float* __restrict__ wv, const float* __restrict__ wo)
{
    size_t e = ((size_t)blockIdx.x * 256 + threadIdx.x) * 4;
    const float* src;
    __nv_bfloat16* dst;
    if (e < (size_t)3 * NX) {
        int s = (int)(e / NX);
        src = (s == 0) ? q : ((s == 1) ? k : v);
        dst = g_Xb + (size_t)s * NX;
        e -= (size_t)s * NX;
    } else {
        size_t r = e - (size_t)3 * NX;
        int s = (int)(r / NW);
        src = (s == 0) ? wq : ((s == 1) ? wk : ((s == 2) ? wv : wo));
        dst = g_Wb + (size_t)s * NW;
        e = r - (size_t)s * NW;
    }
    float4 x = *(const float4*)(src + e);
    *(__nv_bfloat162*)(dst + e)     = __float22bfloat162_rn(make_float2(x.x, x.y));
    *(__nv_bfloat162*)(dst + e + 2) = __float22bfloat162_rn(make_float2(x.z, x.w));
}

// ---------------------------------------------------------------------------
// Shared GEMM mainloop (R13 configuration — measured best):
// C[128x128] = A[128xD] @ B[128xD]^T (NT), bf16 mma. BK=32, 4-stage
// cp.async pipeline (wait_group 2); pitch-20-word smem rows (ldmatrix
// phases conflict-free); per-kt fragment batch: all 24 LDSM before the
// 32 mmas. 8 warps, 64x32 warp tiles.
// Stage layout: [A 128*20 | B 128*20] words, stride 5120 words = 20480 B.
// ---------------------------------------------------------------------------
#define GEMM_SMEM (4 * 5120 * 4)   // 81920 B

__device__ __forceinline__ void gemm_mainloop(
    const __nv_bfloat16* __restrict__ Ablk,   // + m0*D_
    const __nv_bfloat16* __restrict__ Bblk,   // + n0*D_
    float acc[4][4][4])
{
    extern __shared__ unsigned smem_u[];
    const unsigned sbase = (unsigned)__cvta_generic_to_shared(smem_u);
    const int t = threadIdx.x;
    const int warp = t >> 5, l = t & 31;
    const int wm = (warp >> 2) * 64, wn = (warp & 3) * 32;

    // loaders: thread t -> row t>>2 (and +64), 16B chunk t&3
    const int lrow = t >> 2, lch = t & 3;
    const __nv_bfloat16* gA0 = Ablk + (size_t)lrow * D_ + lch * 8;
    const __nv_bfloat16* gA1 = gA0 + (size_t)64 * D_;
    const __nv_bfloat16* gB0 = Bblk + (size_t)lrow * D_ + lch * 8;
    const __nv_bfloat16* gB1 = gB0 + (size_t)64 * D_;
    const unsigned sA0 = sbase + (lrow * 20 + lch * 4) * 4;
    const unsigned sA1 = sA0 + 64 * 80;
    const unsigned sB0 = sA0 + 2560 * 4;
    const unsigned sB1 = sB0 + 64 * 80;

    // ldmatrix lane addressing (word offsets within a stage)
    const int arow = (l & 7) + 8 * ((l >> 3) & 1);   // A: m8-pair select
    const int acw  = 4 * (l >> 4);                   // A: k16-half select
    const int brow = (l & 7) + 8 * (l >> 4);         // B: n8-pair select
    const int bcw  = 4 * ((l >> 3) & 1);             // B: k16-half select

#pragma unroll
    for (int mt = 0; mt < 4; mt++)
#pragma unroll
        for (int nt = 0; nt < 4; nt++)
#pragma unroll
            for (int i = 0; i < 4; i++) acc[mt][nt][i] = 0.f;

    // prefetch stages 0..2
#pragma unroll
    for (int s = 0; s < 3; s++) {
        const int ko = s * 32;
        const unsigned so = s * 20480;
        cpa16(sA0 + so, gA0 + ko); cpa16(sA1 + so, gA1 + ko);
        cpa16(sB0 + so, gB0 + ko); cpa16(sB1 + so, gB1 + ko);
        asm volatile("cp.async.commit_group;\n" ::: "memory");
    }

#pragma unroll 1
    for (int kt = 0; kt < 32; kt++) {
        if (kt < 30)       asm volatile("cp.async.wait_group 2;\n" ::: "memory");
        else if (kt == 30) asm volatile("cp.async.wait_group 1;\n" ::: "memory");
        else               asm volatile("cp.async.wait_group 0;\n" ::: "memory");
        __syncthreads();
        if (kt + 3 < 32) {
            const int ko = (kt + 3) * 32;
            const unsigned so = ((kt + 3) & 3) * 20480;
            cpa16(sA0 + so, gA0 + ko); cpa16(sA1 + so, gA1 + ko);
            cpa16(sB0 + so, gB0 + ko); cpa16(sB1 + so, gB1 + ko);
            asm volatile("cp.async.commit_group;\n" ::: "memory");
        }
        const unsigned stA = sbase + (kt & 3) * 20480;
        const unsigned stB = stA + 2560 * 4;

        // batch ALL fragment loads for both ks-steps first
        unsigned af[2][4][4], bq[2][2][4];
#pragma unroll
        for (int ks = 0; ks < 2; ks++) {
#pragma unroll
            for (int mt = 0; mt < 4; mt++)
                ldsm4(af[ks][mt],
                      stA + ((wm + mt * 16 + arow) * 20 + ks * 8 + acw) * 4);
#pragma unroll
            for (int p = 0; p < 2; p++)
                ldsm4(bq[ks][p],
                      stB + ((wn + p * 16 + brow) * 20 + ks * 8 + bcw) * 4);
        }
        // then the full mma stream
#pragma unroll
        for (int ks = 0; ks < 2; ks++)
#pragma unroll
            for (int mt = 0; mt < 4; mt++)
#pragma unroll
                for (int nt = 0; nt < 4; nt++) {
                    unsigned bfr[2] = { bq[ks][nt >> 1][(nt & 1) * 2],
                                        bq[ks][nt >> 1][(nt & 1) * 2 + 1] };
                    mma16(acc[mt][nt], af[ks][mt], bfr);
                }
    }
}

// ---------------------------------------------------------------------------
// QKV projection: O = X @ W^T; epilogue remaps to [b,h,s,64] bf16,
// Q folds 0.125*log2(e).
// ---------------------------------------------------------------------------
__global__ __launch_bounds__(256, 2) void proj_kernel()
{
    const int z = blockIdx.z;
    const __nv_bfloat16* X = g_Xb + (size_t)z * NX;
    const __nv_bfloat16* W = g_Wb + (size_t)z * NW;
    __nv_bfloat16* O = (z == 0) ? g_Qh : ((z == 1) ? g_Kh : g_Vh);
    const float scale = (z == 0) ? 0.125f * LOG2E : 1.0f;

    const int m0 = blockIdx.y * 128, n0 = blockIdx.x * 128;
    float acc[4][4][4];
    gemm_mainloop(X + (size_t)m0 * D_, W + (size_t)n0 * D_, acc);

    const int t = threadIdx.x;
    const int warp = t >> 5, l = t & 31, g = l >> 2, t4 = l & 3;
    const int wm = (warp >> 2) * 64, wn = (warp & 3) * 32;
#pragma unroll
    for (int mt = 0; mt < 4; mt++) {
        const int row = m0 + wm + mt * 16 + g;
        const int bb = row >> 11, s = row & 2047;
#pragma unroll
        for (int nt = 0; nt < 4; nt++) {
            const int col = n0 + wn + nt * 8 + 2 * t4;
            const int h = col >> 6, cl = col & 63;
            *(unsigned*)&O[(((size_t)bb * H_ + h) * S_ + s) * 64 + cl] =
                pk2(acc[mt][nt][0] * scale, acc[mt][nt][1] * scale);
            *(unsigned*)&O[(((size_t)bb * H_ + h) * S_ + (s + 8)) * 64 + cl] =
                pk2(acc[mt][nt][2] * scale, acc[mt][nt][3] * scale);
        }
    }
}

// ---------------------------------------------------------------------------
// Output projection + residual: out = ctx @ Wo^T + resid (fp32 out)
// ---------------------------------------------------------------------------
__global__ __launch_bounds__(256, 2) void oproj_kernel(
    const float* __restrict__ resid, float* __restrict__ out)
{
    const int m0 = blockIdx.y * 128, n0 = blockIdx.x * 128;
    float acc[4][4][4];
    gemm_mainloop(g_ctx + (size_t)m0 * D_,
                  g_Wb + (size_t)3 * NW + (size_t)n0 * D_, acc);

    const int t = threadIdx.x;
    const int warp = t >> 5, l = t & 31, g = l >> 2, t4 = l & 3;
    const int wm = (warp >> 2) * 64, wn = (warp & 3) * 32;
#pragma unroll
    for (int mt = 0; mt < 4; mt++) {
        const int row = m0 + wm + mt * 16 + g;
#pragma unroll
        for (int nt = 0; nt < 4; nt++) {
            const int col = n0 + wn + nt * 8 + 2 * t4;
            float2 r0 = *(const float2*)&resid[(size_t)row * D_ + col];
            float2 r1 = *(const float2*)&resid[(size_t)(row + 8) * D_ + col];
            *(float2*)&out[(size_t)row * D_ + col] =
                make_float2(acc[mt][nt][0] + r0.x, acc[mt][nt][1] + r0.y);
            *(float2*)&out[(size_t)(row + 8) * D_ + col] =
                make_float2(acc[mt][nt][2] + r1.x, acc[mt][nt][3] + r1.y);
        }
    }
}

// ---------------------------------------------------------------------------
// Flash attention, bf16 m16n8k16. 128-query tile, 8 warps (bit-identical
// output to the 64-tile version — verified R15; half the K/V staging).
// ---------------------------------------------------------------------------
__global__ __launch_bounds__(256) void attn_kernel(const int* __restrict__ sen_len)
{
    __shared__ unsigned Ks[64 * 36];    // [key][d-pairs]
    __shared__ unsigned VsT[64 * 36];   // [d][key-pairs]

    const int bh = blockIdx.y;
    const int b = bh >> 4, h = bh & 15;
    const int q0 = blockIdx.x * 128;
    const __nv_bfloat16* Qg = g_Qh + (size_t)bh * S_ * 64;
    const __nv_bfloat16* Kg = g_Kh + (size_t)bh * S_ * 64;
    const __nv_bfloat16* Vg = g_Vh + (size_t)bh * S_ * 64;
    const int sen = sen_len[b];
    const int kv_len = min(q0 + 128, sen);

    const int t = threadIdx.x;
    const int warp = t >> 5, l = t & 31, g = l >> 2, t4 = l & 3;
    const int wq = warp * 16;
    const int row0 = q0 + wq + g, row1 = row0 + 8;

    unsigned qa[4][4];
    {
        const __nv_bfloat16* Qr0 = Qg + (size_t)row0 * 64;
        const __nv_bfloat16* Qr1 = Qg + (size_t)row1 * 64;
#pragma unroll
        for (int kt = 0; kt < 4; kt++) {
            qa[kt][0] = *(const unsigned*)&Qr0[16 * kt + 2 * t4];
            qa[kt][1] = *(const unsigned*)&Qr1[16 * kt + 2 * t4];
            qa[kt][2] = *(const unsigned*)&Qr0[16 * kt + 8 + 2 * t4];
            qa[kt][3] = *(const unsigned*)&Qr1[16 * kt + 8 + 2 * t4];
        }
    }

    float oacc[8][4];
#pragma unroll
    for (int nt = 0; nt < 8; nt++)
#pragma unroll
        for (int i = 0; i < 4; i++) oacc[nt][i] = 0.f;
    float m0r = -1e30f, m1r = -1e30f, l0r = 0.f, l1r = 0.f;

    const int kp = t & 31, db = t >> 5;   // V-transpose: key-pair, d-block

    for (int k0 = 0; k0 < kv_len; k0 += 64) {
        __syncthreads();
        // K: straight copy, 256 threads x 2 chunks
#pragma unroll
        for (int it = 0; it < 2; it++) {
            const int f = t + it * 256;
            const int row = f >> 3, qd = f & 7;
            *(uint4*)&Ks[row * 36 + qd * 4] =
                *(const uint4*)&Kg[(size_t)(k0 + row) * 64 + qd * 8];
        }
        // V: transpose during staging (each warp owns one 8-wide d-block)
        {
            union { uint4 u; unsigned short s[8]; } r0, r1;
            r0.u = *(const uint4*)&Vg[(size_t)(k0 + 2 * kp) * 64 + db * 8];
            r1.u = *(const uint4*)&Vg[(size_t)(k0 + 2 * kp + 1) * 64 + db * 8];
#pragma unroll
            for (int j = 0; j < 8; j++)
                VsT[(db * 8 + j) * 36 + kp] =
                    (unsigned)r0.s[j] | ((unsigned)r1.s[j] << 16);
        }
        __syncthreads();

        float sacc[8][4];
#pragma unroll
        for (int nt = 0; nt < 8; nt++)
#pragma unroll
            for (int i = 0; i < 4; i++) sacc[nt][i] = 0.f;
#pragma unroll
        for (int kt = 0; kt < 4; kt++)
#pragma unroll
            for (int nt = 0; nt < 8; nt++) {
                unsigned bf[2];
                bf[0] = Ks[(nt * 8 + g) * 36 + kt * 8 + t4];
                bf[1] = Ks[(nt * 8 + g) * 36 + kt * 8 + t4 + 4];
                mma16(sacc[nt], qa[kt], bf);
            }

        if ((k0 + 63 > row0 - g) || (k0 + 64 > sen)) {
#pragma unroll
            for (int nt = 0; nt < 8; nt++) {
                const int c = k0 + nt * 8 + 2 * t4;
                if (c > row0     || c >= sen)     sacc[nt][0] = -1e9f;
                if (c + 1 > row0 || c + 1 >= sen) sacc[nt][1] = -1e9f;
                if (c > row1     || c >= sen)     sacc[nt][2] = -1e9f;
                if (c + 1 > row1 || c + 1 >= sen) sacc[nt][3] = -1e9f;
            }
        }

        float tm0 = -1e30f, tm1 = -1e30f;
#pragma unroll
        for (int nt = 0; nt < 8; nt++) {
            tm0 = fmaxf(tm0, fmaxf(sacc[nt][0], sacc[nt][1]));
            tm1 = fmaxf(tm1, fmaxf(sacc[nt][2], sacc[nt][3]));
        }
        tm0 = fmaxf(tm0, __shfl_xor_sync(0xffffffffu, tm0, 1));
        tm0 = fmaxf(tm0, __shfl_xor_sync(0xffffffffu, tm0, 2));
        tm1 = fmaxf(tm1, __shfl_xor_sync(0xffffffffu, tm1, 1));
        tm1 = fmaxf(tm1, __shfl_xor_sync(0xffffffffu, tm1, 2));
        const float mn0 = fmaxf(m0r, tm0), mn1 = fmaxf(m1r, tm1);
        const float a0 = ex2f(m0r - mn0), a1 = ex2f(m1r - mn1);
        m0r = mn0; m1r = mn1;
        float s0 = 0.f, s1 = 0.f;
#pragma unroll
        for (int nt = 0; nt < 8; nt++) {
            float p0 = ex2f(sacc[nt][0] - mn0);
            float p1 = ex2f(sacc[nt][1] - mn0);
            float p2 = ex2f(sacc[nt][2] - mn1);
            float p3 = ex2f(sacc[nt][3] - mn1);
            s0 += p0 + p1; s1 += p2 + p3;
            sacc[nt][0] = p0; sacc[nt][1] = p1; sacc[nt][2] = p2; sacc[nt][3] = p3;
            oacc[nt][0] *= a0; oacc[nt][1] *= a0;
            oacc[nt][2] *= a1; oacc[nt][3] *= a1;
        }
        s0 += __shfl_xor_sync(0xffffffffu, s0, 1);
        s0 += __shfl_xor_sync(0xffffffffu, s0, 2);
        s1 += __shfl_xor_sync(0xffffffffu, s1, 1);
        s1 += __shfl_xor_sync(0xffffffffu, s1, 2);
        l0r = l0r * a0 + s0;
        l1r = l1r * a1 + s1;

#pragma unroll
        for (int kt = 0; kt < 4; kt++) {
            unsigned pa[4];
            pa[0] = pk2(sacc[2 * kt][0],     sacc[2 * kt][1]);
            pa[1] = pk2(sacc[2 * kt][2],     sacc[2 * kt][3]);
            pa[2] = pk2(sacc[2 * kt + 1][0], sacc[2 * kt + 1][1]);
            pa[3] = pk2(sacc[2 * kt + 1][2], sacc[2 * kt + 1][3]);
#pragma unroll
            for (int nt = 0; nt < 8; nt++) {
                unsigned bf[2];
                bf[0] = VsT[(nt * 8 + g) * 36 + kt * 8 + t4];
                bf[1] = VsT[(nt * 8 + g) * 36 + kt * 8 + t4 + 4];
                mma16(oacc[nt], pa, bf);
            }
        }
    }

    const float inv0 = 1.f / l0r, inv1 = 1.f / l1r;
#pragma unroll
    for (int nt = 0; nt < 8; nt++) {
        const int cl = h * 64 + nt * 8 + 2 * t4;
        *(unsigned*)&g_ctx[((size_t)b * S_ + row0) * D_ + cl] =
            pk2(oacc[nt][0] * inv0, oacc[nt][1] * inv0);
        *(unsigned*)&g_ctx[((size_t)b * S_ + row1) * D_ + cl] =
            pk2(oacc[nt][2] * inv1, oacc[nt][3] * inv1);
    }
}

// ---------------------------------------------------------------------------
// LayerNorm (biased variance), in place. One block per 1024-elem row.
// ---------------------------------------------------------------------------
__global__ __launch_bounds__(256) void ln_kernel(
    float* __restrict__ out, const float* __restrict__ gamma,
    const float* __restrict__ beta)
{
    __shared__ float sbuf[8], ssbuf[8], red[2];
    const int row = blockIdx.x;
    float* p = out + (size_t)row * D_;
    const int t = threadIdx.x;

    float4 x = *(const float4*)&p[t * 4];
    float s  = x.x + x.y + x.z + x.w;
    float ss = x.x * x.x + x.y * x.y + x.z * x.z + x.w * x.w;
#pragma unroll
    for (int off = 16; off; off >>= 1) {
        s  += __shfl_xor_sync(0xffffffffu, s, off);
        ss += __shfl_xor_sync(0xffffffffu, ss, off);
    }
    if ((t & 31) == 0) { sbuf[t >> 5] = s; ssbuf[t >> 5] = ss; }
    __syncthreads();
    if (t == 0) {
        float S = 0.f, SS = 0.f;
        for (int i = 0; i < 8; i++) { S += sbuf[i]; SS += ssbuf[i]; }
        red[0] = S; red[1] = SS;
    }
    __syncthreads();
    float mean = red[0] * (1.f / 1024.f);
    float var  = red[1] * (1.f / 1024.f) - mean * mean;
    float inv  = rsqrtf(var + 1e-5f);

    float4 gg = *(const float4*)&gamma[t * 4];
    float4 bb = *(const float4*)&beta[t * 4];
    float4 y;
    y.x = (x.x - mean) * inv * gg.x + bb.x;
    y.y = (x.y - mean) * inv * gg.y + bb.y;
    y.z = (x.z - mean) * inv * gg.z + bb.z;
    y.w = (x.w - mean) * inv * gg.w + bb.w;
    *(float4*)&p[t * 4] = y;
}

// ---------------------------------------------------------------------------
extern "C" void kernel_launch(void* const* d_in, const int* in_sizes, int n_in,
                              void* d_out, int out_size)
{
    const float* q     = (const float*)d_in[0];
    const float* k     = (const float*)d_in[1];
    const float* v     = (const float*)d_in[2];
    const float* Wq    = (const float*)d_in[3];
    const float* Wk    = (const float*)d_in[4];
    const float* Wv    = (const float*)d_in[5];
    const float* Wo    = (const float*)d_in[6];
    const float* gamma = (const float*)d_in[7];
    const float* beta  = (const float*)d_in[8];
    const int*   sen   = (const int*)d_in[9];
    float* out = (float*)d_out;

    cudaFuncSetAttribute(proj_kernel,
                         cudaFuncAttributeMaxDynamicSharedMemorySize, GEMM_SMEM);
    cudaFuncSetAttribute(oproj_kernel,
                         cudaFuncAttributeMaxDynamicSharedMemorySize, GEMM_SMEM);

    conv_kernel<<<(3 * NX + 4 * NW) / (4 * 256), 256>>>(q, k, v, Wq, Wk, Wv, Wo);
    proj_kernel<<<dim3(D_ / 128, ROWS / 128, 3), 256, GEMM_SMEM>>>();
    attn_kernel<<<dim3(S_ / 128, B_ * H_), 256>>>(sen);
    oproj_kernel<<<dim3(D_ / 128, ROWS / 128), 256, GEMM_SMEM>>>(q, out);
    ln_kernel<<<ROWS, 256>>>(out, gamma, beta);
}